// round 14
// baseline (speedup 1.0000x reference)
#include <cuda_runtime.h>
#include <cuda_fp16.h>
#include <cstdint>
#include <cstddef>

#define BB 4
#define HH 128
#define WW 128
#define NP 9
#define PTOT (BB*HH*WW)

// ---------------------------------------------------------------------------
// Scratch
// ---------------------------------------------------------------------------
__device__ __half g_t1 [(size_t)PTOT * 64];     // fp16
__device__ __half g_t2 [(size_t)PTOT * 128];    // fp16
// all weights fp16, thread-major packed m16n8k16 fragments (4096 halves/tile)
__device__ __half g_wKh[9 * 4096];
__device__ __half g_wVh[9 * 4096];
__device__ __half g_wQh[4096];
__device__ __half g_wF1h[4096];
__device__ __half g_wc2h[18 * 4096];            // [t*2+cb]
__device__ __half g_wc3h[18 * 4096];            // [t*2+ch]

// ---------------------------------------------------------------------------
// helpers
// ---------------------------------------------------------------------------
__device__ __forceinline__ void mma16h(float* c, const uint32_t* a, uint2 b) {
    asm volatile(
        "mma.sync.aligned.m16n8k16.row.col.f32.f16.f16.f32 "
        "{%0,%1,%2,%3}, {%4,%5,%6,%7}, {%8,%9}, {%0,%1,%2,%3};"
        : "+f"(c[0]), "+f"(c[1]), "+f"(c[2]), "+f"(c[3])
        : "r"(a[0]), "r"(a[1]), "r"(a[2]), "r"(a[3]),
          "r"(b.x), "r"(b.y));
}

__device__ __forceinline__ void cp16(void* dst_smem, const void* src) {
    uint32_t d = (uint32_t)__cvta_generic_to_shared(dst_smem);
    asm volatile("cp.async.cg.shared.global [%0], [%1], 16;" :: "r"(d), "l"(src) : "memory");
}
__device__ __forceinline__ void cp_commit() { asm volatile("cp.async.commit_group;" ::: "memory"); }
__device__ __forceinline__ void cp_wait0()  { asm volatile("cp.async.wait_group 0;"  ::: "memory"); }
__device__ __forceinline__ void cp_wait1()  { asm volatile("cp.async.wait_group 1;"  ::: "memory"); }

// fp16 64-wide warp step: m-frag 16 rows, 8 n-frags, K=64 via 4 k16 steps.
__device__ __forceinline__ void gemm64h(float (&acc)[8][4], const uint32_t* Bl,
                                        const __half* A0, const __half* A8)
{
    #pragma unroll
    for (int ks16 = 0; ks16 < 4; ks16++) {
        uint32_t a[4];
        a[0] = *(const uint32_t*)(A0 + ks16 * 16);
        a[1] = *(const uint32_t*)(A8 + ks16 * 16);
        a[2] = *(const uint32_t*)(A0 + ks16 * 16 + 8);
        a[3] = *(const uint32_t*)(A8 + ks16 * 16 + 8);
        #pragma unroll
        for (int nf = 0; nf < 8; nf++) {
            uint2 bv = *(const uint2*)&Bl[(ks16 * 8 + nf) * 64];
            mma16h(acc[nf], a, bv);
        }
    }
}

// pack position (in halves, within a 64x64 tile) for weight element (k, n)
__device__ __forceinline__ size_t packpos(int k, int n) {
    int ks16 = k >> 4, kl = k & 15;
    int nf = n >> 3, colf = n & 7;
    int krel = kl & 7, reg = kl >> 3;
    int lane = colf * 4 + (krel >> 1);
    return (size_t)(((ks16 * 8 + nf) * 64 + lane * 2 + reg) * 2 + (krel & 1));
}

// ---------------------------------------------------------------------------
// Prep: all weights -> fp16 packed fragment tiles
// ---------------------------------------------------------------------------
__global__ __launch_bounds__(256) void prep_w(
    const float* __restrict__ K_P, const float* __restrict__ V_P,
    const float* __restrict__ Q_P, const float* __restrict__ F1,
    const float* __restrict__ W2, const float* __restrict__ W3)
{
    int i = blockIdx.x * 256 + threadIdx.x;
    if (i < 73728) {                               // K_P / V_P [64,576]
        const float* src = (i < 36864) ? K_P : V_P;
        __half* dst = (i < 36864) ? g_wKh : g_wVh;
        int j = (i < 36864) ? i : i - 36864;
        int k = j / 576, n = j % 576;
        int nt = n >> 6, nl = n & 63;
        dst[(size_t)nt * 4096 + packpos(k, nl)] = __float2half_rn(src[j]);
    } else if (i < 81920) {                        // Q_P / ff1 [64,64]
        int j = i - 73728;
        const float* src = (j < 4096) ? Q_P : F1;
        __half* dst = (j < 4096) ? g_wQh : g_wF1h;
        int jj = j & 4095;
        int k = jj >> 6, n = jj & 63;
        dst[packpos(k, n)] = __float2half_rn(src[jj]);
    } else if (i < 155648) {                       // ff2 [9][64][128] -> COUT-split
        int j = i - 81920;
        int t = j >> 13, k = (j >> 7) & 63, n = j & 127;
        int cb = n >> 6, nl = n & 63;
        g_wc2h[(size_t)(t * 2 + cb) * 4096 + packpos(k, nl)] = __float2half_rn(W2[j]);
    } else {                                       // ff3 [9][128][64] -> CIN-chunked
        int j = i - 155648;
        int t = j >> 13, k = (j >> 6) & 127, n = j & 63;
        int ch = k >> 6, kl = k & 63;
        g_wc3h[(size_t)(t * 2 + ch) * 4096 + packpos(kl, n)] = __float2half_rn(W3[j]);
    }
}

// ---------------------------------------------------------------------------
// Fused fp16 attention with online softmax + ff1 (unchanged from R13).
// ---------------------------------------------------------------------------
__global__ __launch_bounds__(256, 2) void attn_fused(
    const float* __restrict__ x,
    const uint32_t* __restrict__ wQ, const uint32_t* __restrict__ wK,
    const uint32_t* __restrict__ wV, const uint32_t* __restrict__ wF1,
    const float* __restrict__ bias1, __half* __restrict__ t1)
{
    constexpr int HW2 = 18, PSTH = 72;
    extern __shared__ char smraw[];
    __half*   haloH = (__half*)smraw;                      // 180*72 halves
    uint32_t* Bf    = (uint32_t*)(smraw + 180 * PSTH * 2); // 4 x 2048 uints

    const int x0 = blockIdx.x * 16;
    const int y0 = blockIdx.y * 8;
    const int b  = blockIdx.z;
    const int tid = threadIdx.x;
    const int warp = tid >> 5, lane = tid & 31;
    const int lr = lane >> 2, lc = lane & 3;

    #pragma unroll
    for (int i = 0; i < 2; i++) { int o = (tid + i * 256) * 4; cp16(Bf + o, wQ + o); }
    cp_commit();
    #pragma unroll
    for (int i = 0; i < 2; i++) { int o = (tid + i * 256) * 4; cp16(Bf + 2048 + o, wK + o); }
    #pragma unroll
    for (int i = 0; i < 2; i++) { int o = (tid + i * 256) * 4; cp16(Bf + 4096 + o, wV + o); }
    cp_commit();

    for (int idx = tid * 4; idx < 180 * 64; idx += 1024) {
        int c = idx & 63;
        int sp = idx >> 6;
        int hy = sp / HW2, hx = sp - hy * HW2;
        int gy = y0 + hy - 1, gx = x0 + hx - 1;
        float4 v = make_float4(0.f, 0.f, 0.f, 0.f);
        if ((unsigned)gy < HH && (unsigned)gx < WW)
            v = *(const float4*)(x + (((size_t)b * HH + gy) * WW + gx) * 64 + c);
        __half2 h01 = __floats2half2_rn(v.x, v.y);
        __half2 h23 = __floats2half2_rn(v.z, v.w);
        *(uint2*)(haloH + sp * PSTH + c) = make_uint2(*(uint32_t*)&h01, *(uint32_t*)&h23);
    }
    cp_wait1();
    __syncthreads();

    const int off0 = (warp * HW2 + lr) * PSTH + 2 * lc;
    const int off8 = (warp * HW2 + lr + 8) * PSTH + 2 * lc;

    uint32_t q16[8][2];
    {
        const int toff = (1 * HW2 + 1) * PSTH;
        float acc[8][4] = {};
        gemm64h(acc, Bf + lane * 2, haloH + off0 + toff, haloH + off8 + toff);
        #pragma unroll
        for (int nf = 0; nf < 8; nf++) {
            __half2 h0 = __floats2half2_rn(acc[nf][0], acc[nf][1]);
            __half2 h1 = __floats2half2_rn(acc[nf][2], acc[nf][3]);
            q16[nf][0] = *(uint32_t*)&h0;
            q16[nf][1] = *(uint32_t*)&h1;
        }
    }

    float mrun[4] = {-1e30f, -1e30f, -1e30f, -1e30f};
    float denom[4] = {0.f, 0.f, 0.f, 0.f};
    float attn[8][4] = {};

    #pragma unroll
    for (int t = 0; t < NP; t++) {
        const int sK = (t & 1) ? 3 : 1;
        const int sV = (t & 1) ? 0 : 2;

        cp_wait0();
        __syncthreads();

        if (t < 8) {
            const int nK = (t & 1) ? 1 : 3;
            const int nV = (t & 1) ? 2 : 0;
            const uint32_t* srcK = wK + (t + 1) * 2048;
            const uint32_t* srcV = wV + (t + 1) * 2048;
            #pragma unroll
            for (int i = 0; i < 2; i++) { int o = (tid + i * 256) * 4; cp16(Bf + nK * 2048 + o, srcK + o); }
            #pragma unroll
            for (int i = 0; i < 2; i++) { int o = (tid + i * 256) * 4; cp16(Bf + nV * 2048 + o, srcV + o); }
            cp_commit();
        } else {
            #pragma unroll
            for (int i = 0; i < 2; i++) { int o = (tid + i * 256) * 4; cp16(Bf + 3 * 2048 + o, wF1 + o); }
            cp_commit();
        }

        const int toff = ((t / 3) * HW2 + (t % 3)) * PSTH;
        const __half* A0 = haloH + off0 + toff;
        const __half* A8 = haloH + off8 + toff;

        float acc[8][4] = {};
        gemm64h(acc, Bf + sK * 2048 + lane * 2, A0, A8);

        float p[4] = {0.f, 0.f, 0.f, 0.f};
        #pragma unroll
        for (int nf = 0; nf < 8; nf++) {
            const int hd = nf >> 2;
            float2 q0 = __half22float2(*(__half2*)&q16[nf][0]);
            float2 q1 = __half22float2(*(__half2*)&q16[nf][1]);
            p[hd]     += acc[nf][0] * q0.x + acc[nf][1] * q0.y;
            p[2 + hd] += acc[nf][2] * q1.x + acc[nf][3] * q1.y;
        }
        float e[4], scale[4];
        #pragma unroll
        for (int v = 0; v < 4; v++) {
            p[v] += __shfl_xor_sync(0xffffffffu, p[v], 1);
            p[v] += __shfl_xor_sync(0xffffffffu, p[v], 2);
            float s = p[v] * (1.0f / 3.0f);
            float mn = fmaxf(mrun[v], s);
            scale[v] = __expf(mrun[v] - mn);
            e[v]     = __expf(s - mn);
            denom[v] = denom[v] * scale[v] + e[v];
            mrun[v]  = mn;
        }

        #pragma unroll
        for (int nf = 0; nf < 8; nf++)
            #pragma unroll
            for (int j = 0; j < 4; j++) acc[nf][j] = 0.f;
        gemm64h(acc, Bf + sV * 2048 + lane * 2, A0, A8);

        #pragma unroll
        for (int nf = 0; nf < 8; nf++) {
            const int hd = nf >> 2;
            attn[nf][0] = attn[nf][0] * scale[hd]     + e[hd]     * acc[nf][0];
            attn[nf][1] = attn[nf][1] * scale[hd]     + e[hd]     * acc[nf][1];
            attn[nf][2] = attn[nf][2] * scale[2 + hd] + e[2 + hd] * acc[nf][2];
            attn[nf][3] = attn[nf][3] * scale[2 + hd] + e[2 + hd] * acc[nf][3];
        }
    }

    float inv[4];
    #pragma unroll
    for (int v = 0; v < 4; v++) inv[v] = 1.0f / denom[v];

    cp_wait0();
    __syncthreads();

    __half* Ast = haloH;
    #pragma unroll
    for (int nf = 0; nf < 8; nf++) {
        const int hd = nf >> 2;
        int col = nf * 8 + lc * 2;
        __half2 h0 = __floats2half2_rn(attn[nf][0] * inv[hd],     attn[nf][1] * inv[hd]);
        __half2 h1 = __floats2half2_rn(attn[nf][2] * inv[2 + hd], attn[nf][3] * inv[2 + hd]);
        *(uint32_t*)&Ast[(warp * 16 + lr) * PSTH + col]     = *(uint32_t*)&h0;
        *(uint32_t*)&Ast[(warp * 16 + lr + 8) * PSTH + col] = *(uint32_t*)&h1;
    }
    __syncthreads();

    float acc[8][4] = {};
    gemm64h(acc, Bf + 3 * 2048 + lane * 2,
            Ast + (warp * 16 + lr) * PSTH + 2 * lc,
            Ast + (warp * 16 + lr + 8) * PSTH + 2 * lc);

    const int ygl = y0 + warp;
    const size_t p0 = ((size_t)b * HH + ygl) * WW + x0 + lr;
    const size_t p1 = p0 + 8;
    #pragma unroll
    for (int nf = 0; nf < 8; nf++) {
        int col = nf * 8 + lc * 2;
        float b0 = bias1[col], b1 = bias1[col + 1];
        __half2 h0 = __floats2half2_rn(fmaxf(acc[nf][0] + b0, 0.f), fmaxf(acc[nf][1] + b1, 0.f));
        __half2 h1 = __floats2half2_rn(fmaxf(acc[nf][2] + b0, 0.f), fmaxf(acc[nf][3] + b1, 0.f));
        *(__half2*)(t1 + p0 * 64 + col) = h0;
        *(__half2*)(t1 + p1 * 64 + col) = h1;
    }
}

// ---------------------------------------------------------------------------
// fp16 3x3 conv, 16x16 pixel tiles, 256 threads (8 warps), MFS=2 per warp.
// Same inner loop as R10 conv; halo/weight traffic per pixel halved.
// __launch_bounds__(256, 2) -> 2 blocks/SM (16 warps).
// grid = (W/16, H/16, B*SPLIT)
// ---------------------------------------------------------------------------
template <int CIN, int COUT_TOT, int SPLIT, bool OUT_HALF>
__global__ __launch_bounds__(256, 2) void conv_fp16(
    const __half* __restrict__ in, const uint32_t* __restrict__ wfrag,
    const float* __restrict__ bias, void* __restrict__ out_)
{
    constexpr int HW2 = 18, PSTH = 72;          // 18x18 halo, fp16 row stride 72
    constexpr int HALO_H = 18 * HW2 * PSTH;     // 23328 halves
    constexpr int CHUNKS = CIN / 64;
    constexpr int WTAP = 2048;                  // uints per tap-tile
    constexpr int CPT = WTAP / 4 / 256;         // 2 cp16/thread
    constexpr int MFS = 2;

    extern __shared__ char smraw[];
    __half*   haloH = (__half*)smraw;
    uint32_t* Bf    = (uint32_t*)(smraw + HALO_H * 2);  // 2 x WTAP

    const int x0 = blockIdx.x * 16;
    const int y0 = blockIdx.y * 16;
    const int b  = blockIdx.z / SPLIT;
    const int cb = blockIdx.z % SPLIT;
    const int co0 = cb * 64;
    const int tid = threadIdx.x;
    const int warp = tid >> 5, lane = tid & 31;
    const int lr = lane >> 2, lc = lane & 3;

    float acc[MFS][8][4] = {};

    int pixoff[MFS][2];
    #pragma unroll
    for (int mf = 0; mf < MFS; mf++)
        #pragma unroll
        for (int r8 = 0; r8 < 2; r8++) {
            int m = warp * 32 + mf * 16 + r8 * 8 + lr;   // 0..255
            int py = m >> 4, px = m & 15;
            pixoff[mf][r8] = (py * HW2 + px) * PSTH;
        }

    for (int ch = 0; ch < CHUNKS; ch++) {
        const int cin0 = ch * 64;
        __syncthreads();   // prior chunk fully consumed

        // prime tap 0 weights (overlaps halo staging)
        {
            const uint32_t* src = wfrag + (size_t)(0 * CHUNKS * SPLIT + ch * SPLIT + cb) * WTAP;
            #pragma unroll
            for (int i = 0; i < CPT; i++) { int o = (tid + i * 256) * 4; cp16(Bf + o, src + o); }
            cp_commit();
        }

        // halo staging (fp16 input, 18x18 spatial)
        for (int idx = tid * 8; idx < 18 * HW2 * 64; idx += 256 * 8) {
            int c = idx & 63;
            int sp = idx >> 6;
            int hy = sp / HW2, hx = sp - hy * HW2;
            int gy = y0 + hy - 1, gx = x0 + hx - 1;
            uint4 v = make_uint4(0u, 0u, 0u, 0u);
            if ((unsigned)gy < HH && (unsigned)gx < WW)
                v = *(const uint4*)(in + (((size_t)b * HH + gy) * WW + gx) * CIN + cin0 + c);
            *(uint4*)(haloH + sp * PSTH + c) = v;
        }
        cp_wait0();
        __syncthreads();

        for (int t = 0; t < 9; t++) {
            if (t < 8) {
                uint32_t* nb = Bf + ((t + 1) & 1) * WTAP;
                const uint32_t* src = wfrag + (size_t)((t + 1) * CHUNKS * SPLIT + ch * SPLIT + cb) * WTAP;
                #pragma unroll
                for (int i = 0; i < CPT; i++) { int o = (tid + i * 256) * 4; cp16(nb + o, src + o); }
                cp_commit();
            }

            const uint32_t* Bc = Bf + (t & 1) * WTAP;
            const int toff = ((t / 3) * HW2 + (t % 3)) * PSTH;

            #pragma unroll
            for (int ks16 = 0; ks16 < 4; ks16++) {
                uint32_t a[MFS][4];
                #pragma unroll
                for (int mf = 0; mf < MFS; mf++) {
                    const __half* b0 = haloH + pixoff[mf][0] + toff + ks16 * 16 + 2 * lc;
                    const __half* b1 = haloH + pixoff[mf][1] + toff + ks16 * 16 + 2 * lc;
                    a[mf][0] = *(const uint32_t*)b0;
                    a[mf][1] = *(const uint32_t*)b1;
                    a[mf][2] = *(const uint32_t*)(b0 + 8);
                    a[mf][3] = *(const uint32_t*)(b1 + 8);
                }
                #pragma unroll
                for (int nf = 0; nf < 8; nf++) {
                    uint2 bv = *(const uint2*)&Bc[(ks16 * 8 + nf) * 64 + lane * 2];
                    #pragma unroll
                    for (int mf = 0; mf < MFS; mf++)
                        mma16h(acc[mf][nf], a[mf], bv);
                }
            }

            if (t < 8) { cp_wait0(); __syncthreads(); }
        }
    }

    // epilogue: bias + relu
    #pragma unroll
    for (int mf = 0; mf < MFS; mf++) {
        #pragma unroll
        for (int r8 = 0; r8 < 2; r8++) {
            int m = warp * 32 + mf * 16 + r8 * 8 + lr;
            int py = m >> 4, px = m & 15;
            int y = y0 + py, xx = x0 + px;
            size_t base = (((size_t)b * HH + y) * WW + xx) * COUT_TOT + co0;
            #pragma unroll
            for (int nf = 0; nf < 8; nf++) {
                int n = nf * 8 + lc * 2;
                float vx = fmaxf(acc[mf][nf][r8 * 2 + 0] + bias[co0 + n], 0.f);
                float vy = fmaxf(acc[mf][nf][r8 * 2 + 1] + bias[co0 + n + 1], 0.f);
                if (OUT_HALF) {
                    __half2 h = __floats2half2_rn(vx, vy);
                    *(__half2*)((__half*)out_ + base + n) = h;
                } else {
                    *(float2*)((float*)out_ + base + n) = make_float2(vx, vy);
                }
            }
        }
    }
}

// ---------------------------------------------------------------------------
// Launch
// ---------------------------------------------------------------------------
extern "C" void kernel_launch(void* const* d_in, const int* in_sizes, int n_in,
                              void* d_out, int out_size)
{
    const float* x      = (const float*)d_in[0];
    const float* K_P    = (const float*)d_in[1];
    const float* V_P    = (const float*)d_in[2];
    const float* Q_P    = (const float*)d_in[3];
    const float* ff1_k  = (const float*)d_in[4];
    const float* ff1_b  = (const float*)d_in[5];
    const float* ff2_k  = (const float*)d_in[6];
    const float* ff2_b  = (const float*)d_in[7];
    const float* ff3_k  = (const float*)d_in[8];
    const float* ff3_b  = (const float*)d_in[9];
    float* out = (float*)d_out;

    __half *t1, *t2, *wKh, *wVh, *wQh, *wF1h, *wc2h, *wc3h;
    cudaGetSymbolAddress((void**)&t1,   g_t1);
    cudaGetSymbolAddress((void**)&t2,   g_t2);
    cudaGetSymbolAddress((void**)&wKh,  g_wKh);
    cudaGetSymbolAddress((void**)&wVh,  g_wVh);
    cudaGetSymbolAddress((void**)&wQh,  g_wQh);
    cudaGetSymbolAddress((void**)&wF1h, g_wF1h);
    cudaGetSymbolAddress((void**)&wc2h, g_wc2h);
    cudaGetSymbolAddress((void**)&wc3h, g_wc3h);

    const int FUSED_SMEM = 180 * 72 * 2 + 4 * 2048 * 4;      // 58688
    const int CONV_SMEM  = 18 * 18 * 72 * 2 + 2 * 2048 * 4;  // 63040

    cudaFuncSetAttribute(attn_fused, cudaFuncAttributeMaxDynamicSharedMemorySize, FUSED_SMEM);
    cudaFuncSetAttribute((conv_fp16<64, 128, 2, true>),  cudaFuncAttributeMaxDynamicSharedMemorySize, CONV_SMEM);
    cudaFuncSetAttribute((conv_fp16<128, 64, 1, false>), cudaFuncAttributeMaxDynamicSharedMemorySize, CONV_SMEM);

    prep_w<<<896, 256>>>(K_P, V_P, Q_P, ff1_k, ff2_k, ff3_k);

    // Fused fp16 projections + online-softmax attention + ff1
    attn_fused<<<dim3(WW / 16, HH / 8, BB), 256, FUSED_SMEM>>>(
        x, (const uint32_t*)wQh, (const uint32_t*)wKh, (const uint32_t*)wVh,
        (const uint32_t*)wF1h, ff1_b, t1);

    // fp16 convs, 16x16 tiles
    conv_fp16<64, 128, 2, true><<<dim3(WW / 16, HH / 16, BB * 2), 256, CONV_SMEM>>>(
        t1, (const uint32_t*)wc2h, ff2_b, t2);
    conv_fp16<128, 64, 1, false><<<dim3(WW / 16, HH / 16, BB), 256, CONV_SMEM>>>(
        t2, (const uint32_t*)wc3h, ff3_b, out);
}

// round 16
// speedup vs baseline: 1.0321x; 1.0321x over previous
#include <cuda_runtime.h>
#include <cuda_fp16.h>
#include <cstdint>
#include <cstddef>

#define BB 4
#define HH 128
#define WW 128
#define NP 9
#define PTOT (BB*HH*WW)

// ---------------------------------------------------------------------------
// Scratch
// ---------------------------------------------------------------------------
__device__ __half g_t1 [(size_t)PTOT * 64];     // fp16
__device__ __half g_t2 [(size_t)PTOT * 128];    // fp16
// all weights fp16, thread-major packed m16n8k16 fragments (4096 halves/tile)
__device__ __half g_wKh[9 * 4096];
__device__ __half g_wVh[9 * 4096];
__device__ __half g_wQh[4096];
__device__ __half g_wF1h[4096];
__device__ __half g_wc2h[18 * 4096];            // [t*2+cb]
__device__ __half g_wc3h[18 * 4096];            // [t*2+ch]

// ---------------------------------------------------------------------------
// helpers
// ---------------------------------------------------------------------------
__device__ __forceinline__ void mma16h(float* c, const uint32_t* a, uint2 b) {
    asm volatile(
        "mma.sync.aligned.m16n8k16.row.col.f32.f16.f16.f32 "
        "{%0,%1,%2,%3}, {%4,%5,%6,%7}, {%8,%9}, {%0,%1,%2,%3};"
        : "+f"(c[0]), "+f"(c[1]), "+f"(c[2]), "+f"(c[3])
        : "r"(a[0]), "r"(a[1]), "r"(a[2]), "r"(a[3]),
          "r"(b.x), "r"(b.y));
}

__device__ __forceinline__ void cp16(void* dst_smem, const void* src) {
    uint32_t d = (uint32_t)__cvta_generic_to_shared(dst_smem);
    asm volatile("cp.async.cg.shared.global [%0], [%1], 16;" :: "r"(d), "l"(src) : "memory");
}
__device__ __forceinline__ void cp_commit() { asm volatile("cp.async.commit_group;" ::: "memory"); }
__device__ __forceinline__ void cp_wait0()  { asm volatile("cp.async.wait_group 0;"  ::: "memory"); }
__device__ __forceinline__ void cp_wait1()  { asm volatile("cp.async.wait_group 1;"  ::: "memory"); }

// fp16 64-wide warp step: m-frag 16 rows, 8 n-frags, K=64 via 4 k16 steps.
__device__ __forceinline__ void gemm64h(float (&acc)[8][4], const uint32_t* Bl,
                                        const __half* A0, const __half* A8)
{
    #pragma unroll
    for (int ks16 = 0; ks16 < 4; ks16++) {
        uint32_t a[4];
        a[0] = *(const uint32_t*)(A0 + ks16 * 16);
        a[1] = *(const uint32_t*)(A8 + ks16 * 16);
        a[2] = *(const uint32_t*)(A0 + ks16 * 16 + 8);
        a[3] = *(const uint32_t*)(A8 + ks16 * 16 + 8);
        #pragma unroll
        for (int nf = 0; nf < 8; nf++) {
            uint2 bv = *(const uint2*)&Bl[(ks16 * 8 + nf) * 64];
            mma16h(acc[nf], a, bv);
        }
    }
}

// pack position (in halves, within a 64x64 tile) for weight element (k, n)
__device__ __forceinline__ size_t packpos(int k, int n) {
    int ks16 = k >> 4, kl = k & 15;
    int nf = n >> 3, colf = n & 7;
    int krel = kl & 7, reg = kl >> 3;
    int lane = colf * 4 + (krel >> 1);
    return (size_t)(((ks16 * 8 + nf) * 64 + lane * 2 + reg) * 2 + (krel & 1));
}

// ---------------------------------------------------------------------------
// Prep: all weights -> fp16 packed fragment tiles
// ---------------------------------------------------------------------------
__global__ __launch_bounds__(256) void prep_w(
    const float* __restrict__ K_P, const float* __restrict__ V_P,
    const float* __restrict__ Q_P, const float* __restrict__ F1,
    const float* __restrict__ W2, const float* __restrict__ W3)
{
    int i = blockIdx.x * 256 + threadIdx.x;
    if (i < 73728) {                               // K_P / V_P [64,576]
        const float* src = (i < 36864) ? K_P : V_P;
        __half* dst = (i < 36864) ? g_wKh : g_wVh;
        int j = (i < 36864) ? i : i - 36864;
        int k = j / 576, n = j % 576;
        int nt = n >> 6, nl = n & 63;
        dst[(size_t)nt * 4096 + packpos(k, nl)] = __float2half_rn(src[j]);
    } else if (i < 81920) {                        // Q_P / ff1 [64,64]
        int j = i - 73728;
        const float* src = (j < 4096) ? Q_P : F1;
        __half* dst = (j < 4096) ? g_wQh : g_wF1h;
        int jj = j & 4095;
        int k = jj >> 6, n = jj & 63;
        dst[packpos(k, n)] = __float2half_rn(src[jj]);
    } else if (i < 155648) {                       // ff2 [9][64][128] -> COUT-split
        int j = i - 81920;
        int t = j >> 13, k = (j >> 7) & 63, n = j & 127;
        int cb = n >> 6, nl = n & 63;
        g_wc2h[(size_t)(t * 2 + cb) * 4096 + packpos(k, nl)] = __float2half_rn(W2[j]);
    } else {                                       // ff3 [9][128][64] -> CIN-chunked
        int j = i - 155648;
        int t = j >> 13, k = (j >> 6) & 127, n = j & 63;
        int ch = k >> 6, kl = k & 63;
        g_wc3h[(size_t)(t * 2 + ch) * 4096 + packpos(kl, n)] = __float2half_rn(W3[j]);
    }
}

// ---------------------------------------------------------------------------
// Fused fp16 attention with online softmax + ff1 (R13-proven).
// ---------------------------------------------------------------------------
__global__ __launch_bounds__(256, 2) void attn_fused(
    const float* __restrict__ x,
    const uint32_t* __restrict__ wQ, const uint32_t* __restrict__ wK,
    const uint32_t* __restrict__ wV, const uint32_t* __restrict__ wF1,
    const float* __restrict__ bias1, __half* __restrict__ t1)
{
    constexpr int HW2 = 18, PSTH = 72;
    extern __shared__ char smraw[];
    __half*   haloH = (__half*)smraw;                      // 180*72 halves
    uint32_t* Bf    = (uint32_t*)(smraw + 180 * PSTH * 2); // 4 x 2048 uints

    const int x0 = blockIdx.x * 16;
    const int y0 = blockIdx.y * 8;
    const int b  = blockIdx.z;
    const int tid = threadIdx.x;
    const int warp = tid >> 5, lane = tid & 31;
    const int lr = lane >> 2, lc = lane & 3;

    #pragma unroll
    for (int i = 0; i < 2; i++) { int o = (tid + i * 256) * 4; cp16(Bf + o, wQ + o); }
    cp_commit();
    #pragma unroll
    for (int i = 0; i < 2; i++) { int o = (tid + i * 256) * 4; cp16(Bf + 2048 + o, wK + o); }
    #pragma unroll
    for (int i = 0; i < 2; i++) { int o = (tid + i * 256) * 4; cp16(Bf + 4096 + o, wV + o); }
    cp_commit();

    for (int idx = tid * 4; idx < 180 * 64; idx += 1024) {
        int c = idx & 63;
        int sp = idx >> 6;
        int hy = sp / HW2, hx = sp - hy * HW2;
        int gy = y0 + hy - 1, gx = x0 + hx - 1;
        float4 v = make_float4(0.f, 0.f, 0.f, 0.f);
        if ((unsigned)gy < HH && (unsigned)gx < WW)
            v = *(const float4*)(x + (((size_t)b * HH + gy) * WW + gx) * 64 + c);
        __half2 h01 = __floats2half2_rn(v.x, v.y);
        __half2 h23 = __floats2half2_rn(v.z, v.w);
        *(uint2*)(haloH + sp * PSTH + c) = make_uint2(*(uint32_t*)&h01, *(uint32_t*)&h23);
    }
    cp_wait1();
    __syncthreads();

    const int off0 = (warp * HW2 + lr) * PSTH + 2 * lc;
    const int off8 = (warp * HW2 + lr + 8) * PSTH + 2 * lc;

    uint32_t q16[8][2];
    {
        const int toff = (1 * HW2 + 1) * PSTH;
        float acc[8][4] = {};
        gemm64h(acc, Bf + lane * 2, haloH + off0 + toff, haloH + off8 + toff);
        #pragma unroll
        for (int nf = 0; nf < 8; nf++) {
            __half2 h0 = __floats2half2_rn(acc[nf][0], acc[nf][1]);
            __half2 h1 = __floats2half2_rn(acc[nf][2], acc[nf][3]);
            q16[nf][0] = *(uint32_t*)&h0;
            q16[nf][1] = *(uint32_t*)&h1;
        }
    }

    float mrun[4] = {-1e30f, -1e30f, -1e30f, -1e30f};
    float denom[4] = {0.f, 0.f, 0.f, 0.f};
    float attn[8][4] = {};

    #pragma unroll
    for (int t = 0; t < NP; t++) {
        const int sK = (t & 1) ? 3 : 1;
        const int sV = (t & 1) ? 0 : 2;

        cp_wait0();
        __syncthreads();

        if (t < 8) {
            const int nK = (t & 1) ? 1 : 3;
            const int nV = (t & 1) ? 2 : 0;
            const uint32_t* srcK = wK + (t + 1) * 2048;
            const uint32_t* srcV = wV + (t + 1) * 2048;
            #pragma unroll
            for (int i = 0; i < 2; i++) { int o = (tid + i * 256) * 4; cp16(Bf + nK * 2048 + o, srcK + o); }
            #pragma unroll
            for (int i = 0; i < 2; i++) { int o = (tid + i * 256) * 4; cp16(Bf + nV * 2048 + o, srcV + o); }
            cp_commit();
        } else {
            #pragma unroll
            for (int i = 0; i < 2; i++) { int o = (tid + i * 256) * 4; cp16(Bf + 3 * 2048 + o, wF1 + o); }
            cp_commit();
        }

        const int toff = ((t / 3) * HW2 + (t % 3)) * PSTH;
        const __half* A0 = haloH + off0 + toff;
        const __half* A8 = haloH + off8 + toff;

        float acc[8][4] = {};
        gemm64h(acc, Bf + sK * 2048 + lane * 2, A0, A8);

        float p[4] = {0.f, 0.f, 0.f, 0.f};
        #pragma unroll
        for (int nf = 0; nf < 8; nf++) {
            const int hd = nf >> 2;
            float2 q0 = __half22float2(*(__half2*)&q16[nf][0]);
            float2 q1 = __half22float2(*(__half2*)&q16[nf][1]);
            p[hd]     += acc[nf][0] * q0.x + acc[nf][1] * q0.y;
            p[2 + hd] += acc[nf][2] * q1.x + acc[nf][3] * q1.y;
        }
        float e[4], scale[4];
        #pragma unroll
        for (int v = 0; v < 4; v++) {
            p[v] += __shfl_xor_sync(0xffffffffu, p[v], 1);
            p[v] += __shfl_xor_sync(0xffffffffu, p[v], 2);
            float s = p[v] * (1.0f / 3.0f);
            float mn = fmaxf(mrun[v], s);
            scale[v] = __expf(mrun[v] - mn);
            e[v]     = __expf(s - mn);
            denom[v] = denom[v] * scale[v] + e[v];
            mrun[v]  = mn;
        }

        #pragma unroll
        for (int nf = 0; nf < 8; nf++)
            #pragma unroll
            for (int j = 0; j < 4; j++) acc[nf][j] = 0.f;
        gemm64h(acc, Bf + sV * 2048 + lane * 2, A0, A8);

        #pragma unroll
        for (int nf = 0; nf < 8; nf++) {
            const int hd = nf >> 2;
            attn[nf][0] = attn[nf][0] * scale[hd]     + e[hd]     * acc[nf][0];
            attn[nf][1] = attn[nf][1] * scale[hd]     + e[hd]     * acc[nf][1];
            attn[nf][2] = attn[nf][2] * scale[2 + hd] + e[2 + hd] * acc[nf][2];
            attn[nf][3] = attn[nf][3] * scale[2 + hd] + e[2 + hd] * acc[nf][3];
        }
    }

    float inv[4];
    #pragma unroll
    for (int v = 0; v < 4; v++) inv[v] = 1.0f / denom[v];

    cp_wait0();
    __syncthreads();

    __half* Ast = haloH;
    #pragma unroll
    for (int nf = 0; nf < 8; nf++) {
        const int hd = nf >> 2;
        int col = nf * 8 + lc * 2;
        __half2 h0 = __floats2half2_rn(attn[nf][0] * inv[hd],     attn[nf][1] * inv[hd]);
        __half2 h1 = __floats2half2_rn(attn[nf][2] * inv[2 + hd], attn[nf][3] * inv[2 + hd]);
        *(uint32_t*)&Ast[(warp * 16 + lr) * PSTH + col]     = *(uint32_t*)&h0;
        *(uint32_t*)&Ast[(warp * 16 + lr + 8) * PSTH + col] = *(uint32_t*)&h1;
    }
    __syncthreads();

    float acc[8][4] = {};
    gemm64h(acc, Bf + 3 * 2048 + lane * 2,
            Ast + (warp * 16 + lr) * PSTH + 2 * lc,
            Ast + (warp * 16 + lr + 8) * PSTH + 2 * lc);

    const int ygl = y0 + warp;
    const size_t p0 = ((size_t)b * HH + ygl) * WW + x0 + lr;
    const size_t p1 = p0 + 8;
    #pragma unroll
    for (int nf = 0; nf < 8; nf++) {
        int col = nf * 8 + lc * 2;
        float b0 = bias1[col], b1 = bias1[col + 1];
        __half2 h0 = __floats2half2_rn(fmaxf(acc[nf][0] + b0, 0.f), fmaxf(acc[nf][1] + b1, 0.f));
        __half2 h1 = __floats2half2_rn(fmaxf(acc[nf][2] + b0, 0.f), fmaxf(acc[nf][3] + b1, 0.f));
        *(__half2*)(t1 + p0 * 64 + col) = h0;
        *(__half2*)(t1 + p1 * 64 + col) = h1;
    }
}

// ---------------------------------------------------------------------------
// conv2: fp16 3x3 conv, 8x16 tile, 128 threads, COUT split (R13-proven form).
// grid = (W/16, H/8, B*2)
// ---------------------------------------------------------------------------
template <int CIN, int COUT_TOT, int SPLIT, bool OUT_HALF>
__global__ __launch_bounds__(128, 3) void conv_fp16_s(
    const __half* __restrict__ in, const uint32_t* __restrict__ wfrag,
    const float* __restrict__ bias, void* __restrict__ out_)
{
    constexpr int HW2 = 18, PSTH = 72;
    constexpr int HALO_H = 10 * HW2 * PSTH;
    constexpr int CHUNKS = CIN / 64;
    constexpr int WTAP = 2048;
    constexpr int CPT = WTAP / 4 / 128;
    constexpr int MFS = 2;

    extern __shared__ char smraw[];
    __half*   haloH = (__half*)smraw;
    uint32_t* Bf    = (uint32_t*)(smraw + HALO_H * 2);

    const int x0 = blockIdx.x * 16;
    const int y0 = blockIdx.y * 8;
    const int b  = blockIdx.z / SPLIT;
    const int cb = blockIdx.z % SPLIT;
    const int co0 = cb * 64;
    const int tid = threadIdx.x;
    const int warp = tid >> 5, lane = tid & 31;
    const int lr = lane >> 2, lc = lane & 3;

    float acc[MFS][8][4] = {};

    int pixoff[MFS][2];
    #pragma unroll
    for (int mf = 0; mf < MFS; mf++)
        #pragma unroll
        for (int r8 = 0; r8 < 2; r8++) {
            int m = warp * 32 + mf * 16 + r8 * 8 + lr;
            int py = m >> 4, px = m & 15;
            pixoff[mf][r8] = (py * HW2 + px) * PSTH;
        }

    for (int ch = 0; ch < CHUNKS; ch++) {
        const int cin0 = ch * 64;
        __syncthreads();

        {
            const uint32_t* src = wfrag + (size_t)(0 * CHUNKS * SPLIT + ch * SPLIT + cb) * WTAP;
            #pragma unroll
            for (int i = 0; i < CPT; i++) { int o = (tid + i * 128) * 4; cp16(Bf + o, src + o); }
            cp_commit();
        }

        for (int idx = tid * 8; idx < 10 * HW2 * 64; idx += 128 * 8) {
            int c = idx & 63;
            int sp = idx >> 6;
            int hy = sp / HW2, hx = sp - hy * HW2;
            int gy = y0 + hy - 1, gx = x0 + hx - 1;
            uint4 v = make_uint4(0u, 0u, 0u, 0u);
            if ((unsigned)gy < HH && (unsigned)gx < WW)
                v = *(const uint4*)(in + (((size_t)b * HH + gy) * WW + gx) * CIN + cin0 + c);
            *(uint4*)(haloH + sp * PSTH + c) = v;
        }
        cp_wait0();
        __syncthreads();

        for (int t = 0; t < 9; t++) {
            if (t < 8) {
                uint32_t* nb = Bf + ((t + 1) & 1) * WTAP;
                const uint32_t* src = wfrag + (size_t)((t + 1) * CHUNKS * SPLIT + ch * SPLIT + cb) * WTAP;
                #pragma unroll
                for (int i = 0; i < CPT; i++) { int o = (tid + i * 128) * 4; cp16(nb + o, src + o); }
                cp_commit();
            }

            const uint32_t* Bc = Bf + (t & 1) * WTAP;
            const int toff = ((t / 3) * HW2 + (t % 3)) * PSTH;

            #pragma unroll
            for (int ks16 = 0; ks16 < 4; ks16++) {
                uint32_t a[MFS][4];
                #pragma unroll
                for (int mf = 0; mf < MFS; mf++) {
                    const __half* b0 = haloH + pixoff[mf][0] + toff + ks16 * 16 + 2 * lc;
                    const __half* b1 = haloH + pixoff[mf][1] + toff + ks16 * 16 + 2 * lc;
                    a[mf][0] = *(const uint32_t*)b0;
                    a[mf][1] = *(const uint32_t*)b1;
                    a[mf][2] = *(const uint32_t*)(b0 + 8);
                    a[mf][3] = *(const uint32_t*)(b1 + 8);
                }
                #pragma unroll
                for (int nf = 0; nf < 8; nf++) {
                    uint2 bv = *(const uint2*)&Bc[(ks16 * 8 + nf) * 64 + lane * 2];
                    #pragma unroll
                    for (int mf = 0; mf < MFS; mf++)
                        mma16h(acc[mf][nf], a[mf], bv);
                }
            }

            if (t < 8) { cp_wait0(); __syncthreads(); }
        }
    }

    #pragma unroll
    for (int mf = 0; mf < MFS; mf++) {
        #pragma unroll
        for (int r8 = 0; r8 < 2; r8++) {
            int m = warp * 32 + mf * 16 + r8 * 8 + lr;
            int py = m >> 4, px = m & 15;
            int y = y0 + py, xx = x0 + px;
            size_t base = (((size_t)b * HH + y) * WW + xx) * COUT_TOT + co0;
            #pragma unroll
            for (int nf = 0; nf < 8; nf++) {
                int n = nf * 8 + lc * 2;
                float vx = fmaxf(acc[mf][nf][r8 * 2 + 0] + bias[co0 + n], 0.f);
                float vy = fmaxf(acc[mf][nf][r8 * 2 + 1] + bias[co0 + n + 1], 0.f);
                if (OUT_HALF) {
                    __half2 h = __floats2half2_rn(vx, vy);
                    *(__half2*)((__half*)out_ + base + n) = h;
                } else {
                    *(float2*)((float*)out_ + base + n) = make_float2(vx, vy);
                }
            }
        }
    }
}

// ---------------------------------------------------------------------------
// conv3: fp16 3x3 conv, 16x16 tile, 256 threads (R14-proven form).
// grid = (W/16, H/16, B)
// ---------------------------------------------------------------------------
template <int CIN, int COUT_TOT, bool OUT_HALF>
__global__ __launch_bounds__(256, 2) void conv_fp16_l(
    const __half* __restrict__ in, const uint32_t* __restrict__ wfrag,
    const float* __restrict__ bias, void* __restrict__ out_)
{
    constexpr int HW2 = 18, PSTH = 72;
    constexpr int HALO_H = 18 * HW2 * PSTH;
    constexpr int CHUNKS = CIN / 64;
    constexpr int WTAP = 2048;
    constexpr int CPT = WTAP / 4 / 256;
    constexpr int MFS = 2;

    extern __shared__ char smraw[];
    __half*   haloH = (__half*)smraw;
    uint32_t* Bf    = (uint32_t*)(smraw + HALO_H * 2);

    const int x0 = blockIdx.x * 16;
    const int y0 = blockIdx.y * 16;
    const int b  = blockIdx.z;
    const int tid = threadIdx.x;
    const int warp = tid >> 5, lane = tid & 31;
    const int lr = lane >> 2, lc = lane & 3;

    float acc[MFS][8][4] = {};

    int pixoff[MFS][2];
    #pragma unroll
    for (int mf = 0; mf < MFS; mf++)
        #pragma unroll
        for (int r8 = 0; r8 < 2; r8++) {
            int m = warp * 32 + mf * 16 + r8 * 8 + lr;   // 0..255
            int py = m >> 4, px = m & 15;
            pixoff[mf][r8] = (py * HW2 + px) * PSTH;
        }

    for (int ch = 0; ch < CHUNKS; ch++) {
        const int cin0 = ch * 64;
        __syncthreads();

        {
            const uint32_t* src = wfrag + (size_t)(0 * CHUNKS + ch) * WTAP;
            #pragma unroll
            for (int i = 0; i < CPT; i++) { int o = (tid + i * 256) * 4; cp16(Bf + o, src + o); }
            cp_commit();
        }

        for (int idx = tid * 8; idx < 18 * HW2 * 64; idx += 256 * 8) {
            int c = idx & 63;
            int sp = idx >> 6;
            int hy = sp / HW2, hx = sp - hy * HW2;
            int gy = y0 + hy - 1, gx = x0 + hx - 1;
            uint4 v = make_uint4(0u, 0u, 0u, 0u);
            if ((unsigned)gy < HH && (unsigned)gx < WW)
                v = *(const uint4*)(in + (((size_t)b * HH + gy) * WW + gx) * CIN + cin0 + c);
            *(uint4*)(haloH + sp * PSTH + c) = v;
        }
        cp_wait0();
        __syncthreads();

        for (int t = 0; t < 9; t++) {
            if (t < 8) {
                uint32_t* nb = Bf + ((t + 1) & 1) * WTAP;
                const uint32_t* src = wfrag + (size_t)((t + 1) * CHUNKS + ch) * WTAP;
                #pragma unroll
                for (int i = 0; i < CPT; i++) { int o = (tid + i * 256) * 4; cp16(nb + o, src + o); }
                cp_commit();
            }

            const uint32_t* Bc = Bf + (t & 1) * WTAP;
            const int toff = ((t / 3) * HW2 + (t % 3)) * PSTH;

            #pragma unroll
            for (int ks16 = 0; ks16 < 4; ks16++) {
                uint32_t a[MFS][4];
                #pragma unroll
                for (int mf = 0; mf < MFS; mf++) {
                    const __half* b0 = haloH + pixoff[mf][0] + toff + ks16 * 16 + 2 * lc;
                    const __half* b1 = haloH + pixoff[mf][1] + toff + ks16 * 16 + 2 * lc;
                    a[mf][0] = *(const uint32_t*)b0;
                    a[mf][1] = *(const uint32_t*)b1;
                    a[mf][2] = *(const uint32_t*)(b0 + 8);
                    a[mf][3] = *(const uint32_t*)(b1 + 8);
                }
                #pragma unroll
                for (int nf = 0; nf < 8; nf++) {
                    uint2 bv = *(const uint2*)&Bc[(ks16 * 8 + nf) * 64 + lane * 2];
                    #pragma unroll
                    for (int mf = 0; mf < MFS; mf++)
                        mma16h(acc[mf][nf], a[mf], bv);
                }
            }

            if (t < 8) { cp_wait0(); __syncthreads(); }
        }
    }

    #pragma unroll
    for (int mf = 0; mf < MFS; mf++) {
        #pragma unroll
        for (int r8 = 0; r8 < 2; r8++) {
            int m = warp * 32 + mf * 16 + r8 * 8 + lr;
            int py = m >> 4, px = m & 15;
            int y = y0 + py, xx = x0 + px;
            size_t base = (((size_t)b * HH + y) * WW + xx) * COUT_TOT;
            #pragma unroll
            for (int nf = 0; nf < 8; nf++) {
                int n = nf * 8 + lc * 2;
                float vx = fmaxf(acc[mf][nf][r8 * 2 + 0] + bias[n], 0.f);
                float vy = fmaxf(acc[mf][nf][r8 * 2 + 1] + bias[n + 1], 0.f);
                if (OUT_HALF) {
                    __half2 h = __floats2half2_rn(vx, vy);
                    *(__half2*)((__half*)out_ + base + n) = h;
                } else {
                    *(float2*)((float*)out_ + base + n) = make_float2(vx, vy);
                }
            }
        }
    }
}

// ---------------------------------------------------------------------------
// Launch
// ---------------------------------------------------------------------------
extern "C" void kernel_launch(void* const* d_in, const int* in_sizes, int n_in,
                              void* d_out, int out_size)
{
    const float* x      = (const float*)d_in[0];
    const float* K_P    = (const float*)d_in[1];
    const float* V_P    = (const float*)d_in[2];
    const float* Q_P    = (const float*)d_in[3];
    const float* ff1_k  = (const float*)d_in[4];
    const float* ff1_b  = (const float*)d_in[5];
    const float* ff2_k  = (const float*)d_in[6];
    const float* ff2_b  = (const float*)d_in[7];
    const float* ff3_k  = (const float*)d_in[8];
    const float* ff3_b  = (const float*)d_in[9];
    float* out = (float*)d_out;

    __half *t1, *t2, *wKh, *wVh, *wQh, *wF1h, *wc2h, *wc3h;
    cudaGetSymbolAddress((void**)&t1,   g_t1);
    cudaGetSymbolAddress((void**)&t2,   g_t2);
    cudaGetSymbolAddress((void**)&wKh,  g_wKh);
    cudaGetSymbolAddress((void**)&wVh,  g_wVh);
    cudaGetSymbolAddress((void**)&wQh,  g_wQh);
    cudaGetSymbolAddress((void**)&wF1h, g_wF1h);
    cudaGetSymbolAddress((void**)&wc2h, g_wc2h);
    cudaGetSymbolAddress((void**)&wc3h, g_wc3h);

    const int FUSED_SMEM = 180 * 72 * 2 + 4 * 2048 * 4;      // 58688
    const int CONV2_SMEM = 10 * 18 * 72 * 2 + 2 * 2048 * 4;  // 42304
    const int CONV3_SMEM = 18 * 18 * 72 * 2 + 2 * 2048 * 4;  // 63040

    cudaFuncSetAttribute(attn_fused, cudaFuncAttributeMaxDynamicSharedMemorySize, FUSED_SMEM);
    cudaFuncSetAttribute((conv_fp16_s<64, 128, 2, true>), cudaFuncAttributeMaxDynamicSharedMemorySize, CONV2_SMEM);
    cudaFuncSetAttribute((conv_fp16_l<128, 64, false>),   cudaFuncAttributeMaxDynamicSharedMemorySize, CONV3_SMEM);

    prep_w<<<896, 256>>>(K_P, V_P, Q_P, ff1_k, ff2_k, ff3_k);

    // Fused fp16 projections + online-softmax attention + ff1
    attn_fused<<<dim3(WW / 16, HH / 8, BB), 256, FUSED_SMEM>>>(
        x, (const uint32_t*)wQh, (const uint32_t*)wKh, (const uint32_t*)wVh,
        (const uint32_t*)wF1h, ff1_b, t1);

    // conv2: R13-proven 128-thread form; conv3: R14-proven 256-thread form
    conv_fp16_s<64, 128, 2, true><<<dim3(WW / 16, HH / 8, BB * 2), 128, CONV2_SMEM>>>(
        t1, (const uint32_t*)wc2h, ff2_b, t2);
    conv_fp16_l<128, 64, false><<<dim3(WW / 16, HH / 16, BB), 256, CONV3_SMEM>>>(
        t2, (const uint32_t*)wc3h, ff3_b, out);
}

// round 17
// speedup vs baseline: 1.0905x; 1.0566x over previous
#include <cuda_runtime.h>
#include <cuda_fp16.h>
#include <cstdint>
#include <cstddef>

#define BB 4
#define HH 128
#define WW 128
#define NP 9
#define PTOT (BB*HH*WW)

// ---------------------------------------------------------------------------
// Scratch
// ---------------------------------------------------------------------------
__device__ __half g_t1 [(size_t)PTOT * 64];     // fp16
__device__ __half g_t2 [(size_t)PTOT * 128];    // fp16
// all weights fp16, thread-major packed m16n8k16 fragments (4096 halves/tile)
__device__ __half g_wKh[9 * 4096];
__device__ __half g_wVh[9 * 4096];
__device__ __half g_wQh[4096];
__device__ __half g_wF1h[4096];
__device__ __half g_wc2h[18 * 4096];            // [t*2+cb]
__device__ __half g_wc3h[18 * 4096];            // [t*2+ch]

// ---------------------------------------------------------------------------
// helpers
// ---------------------------------------------------------------------------
__device__ __forceinline__ void mma16h(float* c, const uint32_t* a, uint2 b) {
    asm volatile(
        "mma.sync.aligned.m16n8k16.row.col.f32.f16.f16.f32 "
        "{%0,%1,%2,%3}, {%4,%5,%6,%7}, {%8,%9}, {%0,%1,%2,%3};"
        : "+f"(c[0]), "+f"(c[1]), "+f"(c[2]), "+f"(c[3])
        : "r"(a[0]), "r"(a[1]), "r"(a[2]), "r"(a[3]),
          "r"(b.x), "r"(b.y));
}

__device__ __forceinline__ void cp16(void* dst_smem, const void* src) {
    uint32_t d = (uint32_t)__cvta_generic_to_shared(dst_smem);
    asm volatile("cp.async.cg.shared.global [%0], [%1], 16;" :: "r"(d), "l"(src) : "memory");
}
// cp.async with zero-fill: copies `sz` bytes (0 or 16), zero-fills the rest.
__device__ __forceinline__ void cp16z(void* dst_smem, const void* src, int sz) {
    uint32_t d = (uint32_t)__cvta_generic_to_shared(dst_smem);
    asm volatile("cp.async.cg.shared.global [%0], [%1], 16, %2;"
                 :: "r"(d), "l"(src), "r"(sz) : "memory");
}
__device__ __forceinline__ void cp_commit() { asm volatile("cp.async.commit_group;" ::: "memory"); }
__device__ __forceinline__ void cp_wait0()  { asm volatile("cp.async.wait_group 0;"  ::: "memory"); }
__device__ __forceinline__ void cp_wait1()  { asm volatile("cp.async.wait_group 1;"  ::: "memory"); }

// fp16 64-wide warp step: m-frag 16 rows, 8 n-frags, K=64 via 4 k16 steps.
__device__ __forceinline__ void gemm64h(float (&acc)[8][4], const uint32_t* Bl,
                                        const __half* A0, const __half* A8)
{
    #pragma unroll
    for (int ks16 = 0; ks16 < 4; ks16++) {
        uint32_t a[4];
        a[0] = *(const uint32_t*)(A0 + ks16 * 16);
        a[1] = *(const uint32_t*)(A8 + ks16 * 16);
        a[2] = *(const uint32_t*)(A0 + ks16 * 16 + 8);
        a[3] = *(const uint32_t*)(A8 + ks16 * 16 + 8);
        #pragma unroll
        for (int nf = 0; nf < 8; nf++) {
            uint2 bv = *(const uint2*)&Bl[(ks16 * 8 + nf) * 64];
            mma16h(acc[nf], a, bv);
        }
    }
}

// ---------------------------------------------------------------------------
// Prep: vectorized. One thread -> one packed uint32 (two adjacent-k halves),
// coalesced stores. Tile map: 0-8 K, 9-17 V, 18 Q, 19 ff1, 20-37 c2, 38-55 c3.
// Within tile: uidx -> sec=uidx>>6 (=ks16*8+nf), rem=uidx&63, lane=rem>>1,
// reg=rem&1; k0 = ks16*16 + reg*8 + (lane&3)*2; n = nf*8 + (lane>>2).
// ---------------------------------------------------------------------------
__global__ __launch_bounds__(256) void prep_w(
    const float* __restrict__ K_P, const float* __restrict__ V_P,
    const float* __restrict__ Q_P, const float* __restrict__ F1,
    const float* __restrict__ W2, const float* __restrict__ W3)
{
    const int i = blockIdx.x * 256 + threadIdx.x;   // 0 .. 114687
    const int tile = i >> 11;
    const int uidx = i & 2047;

    const int sec = uidx >> 6;
    const int ks16 = sec >> 3, nf = sec & 7;
    const int rem = uidx & 63;
    const int lane = rem >> 1, reg = rem & 1;
    const int k0 = ks16 * 16 + reg * 8 + (lane & 3) * 2;  // even k of the pair
    const int nl = nf * 8 + (lane >> 2);                  // 0..63 within tile

    const float* src;
    __half* dst;
    int srcN, kofs = 0, nofs = 0;

    if (tile < 9) {                 // K tiles
        src = K_P; dst = g_wKh + (size_t)tile * 4096; srcN = 576; nofs = tile * 64;
    } else if (tile < 18) {         // V tiles
        src = V_P; dst = g_wVh + (size_t)(tile - 9) * 4096; srcN = 576; nofs = (tile - 9) * 64;
    } else if (tile == 18) {        // Q
        src = Q_P; dst = g_wQh; srcN = 64;
    } else if (tile == 19) {        // ff1
        src = F1;  dst = g_wF1h; srcN = 64;
    } else if (tile < 38) {         // c2: [9][64][128], tile=(t,cb)
        int tt = tile - 20;
        int t = tt >> 1, cb = tt & 1;
        src = W2 + (size_t)t * 64 * 128; dst = g_wc2h + (size_t)tt * 4096;
        srcN = 128; nofs = cb * 64;
    } else {                        // c3: [9][128][64], tile=(t,ch)
        int tt = tile - 38;
        int t = tt >> 1, ch = tt & 1;
        src = W3 + (size_t)t * 128 * 64; dst = g_wc3h + (size_t)tt * 4096;
        srcN = 64; kofs = ch * 64;
    }

    const float lo = src[(size_t)(kofs + k0)     * srcN + nofs + nl];
    const float hi = src[(size_t)(kofs + k0 + 1) * srcN + nofs + nl];
    __half2 h = __floats2half2_rn(lo, hi);
    ((uint32_t*)dst)[uidx] = *(uint32_t*)&h;
}

// ---------------------------------------------------------------------------
// Fused fp16 attention with online softmax + ff1 (R13-proven, unchanged).
// ---------------------------------------------------------------------------
__global__ __launch_bounds__(256, 2) void attn_fused(
    const float* __restrict__ x,
    const uint32_t* __restrict__ wQ, const uint32_t* __restrict__ wK,
    const uint32_t* __restrict__ wV, const uint32_t* __restrict__ wF1,
    const float* __restrict__ bias1, __half* __restrict__ t1)
{
    constexpr int HW2 = 18, PSTH = 72;
    extern __shared__ char smraw[];
    __half*   haloH = (__half*)smraw;                      // 180*72 halves
    uint32_t* Bf    = (uint32_t*)(smraw + 180 * PSTH * 2); // 4 x 2048 uints

    const int x0 = blockIdx.x * 16;
    const int y0 = blockIdx.y * 8;
    const int b  = blockIdx.z;
    const int tid = threadIdx.x;
    const int warp = tid >> 5, lane = tid & 31;
    const int lr = lane >> 2, lc = lane & 3;

    #pragma unroll
    for (int i = 0; i < 2; i++) { int o = (tid + i * 256) * 4; cp16(Bf + o, wQ + o); }
    cp_commit();
    #pragma unroll
    for (int i = 0; i < 2; i++) { int o = (tid + i * 256) * 4; cp16(Bf + 2048 + o, wK + o); }
    #pragma unroll
    for (int i = 0; i < 2; i++) { int o = (tid + i * 256) * 4; cp16(Bf + 4096 + o, wV + o); }
    cp_commit();

    for (int idx = tid * 4; idx < 180 * 64; idx += 1024) {
        int c = idx & 63;
        int sp = idx >> 6;
        int hy = sp / HW2, hx = sp - hy * HW2;
        int gy = y0 + hy - 1, gx = x0 + hx - 1;
        float4 v = make_float4(0.f, 0.f, 0.f, 0.f);
        if ((unsigned)gy < HH && (unsigned)gx < WW)
            v = *(const float4*)(x + (((size_t)b * HH + gy) * WW + gx) * 64 + c);
        __half2 h01 = __floats2half2_rn(v.x, v.y);
        __half2 h23 = __floats2half2_rn(v.z, v.w);
        *(uint2*)(haloH + sp * PSTH + c) = make_uint2(*(uint32_t*)&h01, *(uint32_t*)&h23);
    }
    cp_wait1();
    __syncthreads();

    const int off0 = (warp * HW2 + lr) * PSTH + 2 * lc;
    const int off8 = (warp * HW2 + lr + 8) * PSTH + 2 * lc;

    uint32_t q16[8][2];
    {
        const int toff = (1 * HW2 + 1) * PSTH;
        float acc[8][4] = {};
        gemm64h(acc, Bf + lane * 2, haloH + off0 + toff, haloH + off8 + toff);
        #pragma unroll
        for (int nf = 0; nf < 8; nf++) {
            __half2 h0 = __floats2half2_rn(acc[nf][0], acc[nf][1]);
            __half2 h1 = __floats2half2_rn(acc[nf][2], acc[nf][3]);
            q16[nf][0] = *(uint32_t*)&h0;
            q16[nf][1] = *(uint32_t*)&h1;
        }
    }

    float mrun[4] = {-1e30f, -1e30f, -1e30f, -1e30f};
    float denom[4] = {0.f, 0.f, 0.f, 0.f};
    float attn[8][4] = {};

    #pragma unroll
    for (int t = 0; t < NP; t++) {
        const int sK = (t & 1) ? 3 : 1;
        const int sV = (t & 1) ? 0 : 2;

        cp_wait0();
        __syncthreads();

        if (t < 8) {
            const int nK = (t & 1) ? 1 : 3;
            const int nV = (t & 1) ? 2 : 0;
            const uint32_t* srcK = wK + (t + 1) * 2048;
            const uint32_t* srcV = wV + (t + 1) * 2048;
            #pragma unroll
            for (int i = 0; i < 2; i++) { int o = (tid + i * 256) * 4; cp16(Bf + nK * 2048 + o, srcK + o); }
            #pragma unroll
            for (int i = 0; i < 2; i++) { int o = (tid + i * 256) * 4; cp16(Bf + nV * 2048 + o, srcV + o); }
            cp_commit();
        } else {
            #pragma unroll
            for (int i = 0; i < 2; i++) { int o = (tid + i * 256) * 4; cp16(Bf + 3 * 2048 + o, wF1 + o); }
            cp_commit();
        }

        const int toff = ((t / 3) * HW2 + (t % 3)) * PSTH;
        const __half* A0 = haloH + off0 + toff;
        const __half* A8 = haloH + off8 + toff;

        float acc[8][4] = {};
        gemm64h(acc, Bf + sK * 2048 + lane * 2, A0, A8);

        float p[4] = {0.f, 0.f, 0.f, 0.f};
        #pragma unroll
        for (int nf = 0; nf < 8; nf++) {
            const int hd = nf >> 2;
            float2 q0 = __half22float2(*(__half2*)&q16[nf][0]);
            float2 q1 = __half22float2(*(__half2*)&q16[nf][1]);
            p[hd]     += acc[nf][0] * q0.x + acc[nf][1] * q0.y;
            p[2 + hd] += acc[nf][2] * q1.x + acc[nf][3] * q1.y;
        }
        float e[4], scale[4];
        #pragma unroll
        for (int v = 0; v < 4; v++) {
            p[v] += __shfl_xor_sync(0xffffffffu, p[v], 1);
            p[v] += __shfl_xor_sync(0xffffffffu, p[v], 2);
            float s = p[v] * (1.0f / 3.0f);
            float mn = fmaxf(mrun[v], s);
            scale[v] = __expf(mrun[v] - mn);
            e[v]     = __expf(s - mn);
            denom[v] = denom[v] * scale[v] + e[v];
            mrun[v]  = mn;
        }

        #pragma unroll
        for (int nf = 0; nf < 8; nf++)
            #pragma unroll
            for (int j = 0; j < 4; j++) acc[nf][j] = 0.f;
        gemm64h(acc, Bf + sV * 2048 + lane * 2, A0, A8);

        #pragma unroll
        for (int nf = 0; nf < 8; nf++) {
            const int hd = nf >> 2;
            attn[nf][0] = attn[nf][0] * scale[hd]     + e[hd]     * acc[nf][0];
            attn[nf][1] = attn[nf][1] * scale[hd]     + e[hd]     * acc[nf][1];
            attn[nf][2] = attn[nf][2] * scale[2 + hd] + e[2 + hd] * acc[nf][2];
            attn[nf][3] = attn[nf][3] * scale[2 + hd] + e[2 + hd] * acc[nf][3];
        }
    }

    float inv[4];
    #pragma unroll
    for (int v = 0; v < 4; v++) inv[v] = 1.0f / denom[v];

    cp_wait0();
    __syncthreads();

    __half* Ast = haloH;
    #pragma unroll
    for (int nf = 0; nf < 8; nf++) {
        const int hd = nf >> 2;
        int col = nf * 8 + lc * 2;
        __half2 h0 = __floats2half2_rn(attn[nf][0] * inv[hd],     attn[nf][1] * inv[hd]);
        __half2 h1 = __floats2half2_rn(attn[nf][2] * inv[2 + hd], attn[nf][3] * inv[2 + hd]);
        *(uint32_t*)&Ast[(warp * 16 + lr) * PSTH + col]     = *(uint32_t*)&h0;
        *(uint32_t*)&Ast[(warp * 16 + lr + 8) * PSTH + col] = *(uint32_t*)&h1;
    }
    __syncthreads();

    float acc[8][4] = {};
    gemm64h(acc, Bf + 3 * 2048 + lane * 2,
            Ast + (warp * 16 + lr) * PSTH + 2 * lc,
            Ast + (warp * 16 + lr + 8) * PSTH + 2 * lc);

    const int ygl = y0 + warp;
    const size_t p0 = ((size_t)b * HH + ygl) * WW + x0 + lr;
    const size_t p1 = p0 + 8;
    #pragma unroll
    for (int nf = 0; nf < 8; nf++) {
        int col = nf * 8 + lc * 2;
        float b0 = bias1[col], b1 = bias1[col + 1];
        __half2 h0 = __floats2half2_rn(fmaxf(acc[nf][0] + b0, 0.f), fmaxf(acc[nf][1] + b1, 0.f));
        __half2 h1 = __floats2half2_rn(fmaxf(acc[nf][2] + b0, 0.f), fmaxf(acc[nf][3] + b1, 0.f));
        *(__half2*)(t1 + p0 * 64 + col) = h0;
        *(__half2*)(t1 + p1 * 64 + col) = h1;
    }
}

// ---------------------------------------------------------------------------
// conv2: fp16 3x3 conv, 8x16 tile, 128 threads, COUT split (R13 form,
// halo via cp.async-zfill). grid = (W/16, H/8, B*2)
// ---------------------------------------------------------------------------
template <int CIN, int COUT_TOT, int SPLIT, bool OUT_HALF>
__global__ __launch_bounds__(128, 3) void conv_fp16_s(
    const __half* __restrict__ in, const uint32_t* __restrict__ wfrag,
    const float* __restrict__ bias, void* __restrict__ out_)
{
    constexpr int HW2 = 18, PSTH = 72;
    constexpr int HALO_H = 10 * HW2 * PSTH;
    constexpr int CHUNKS = CIN / 64;
    constexpr int WTAP = 2048;
    constexpr int CPT = WTAP / 4 / 128;
    constexpr int MFS = 2;

    extern __shared__ char smraw[];
    __half*   haloH = (__half*)smraw;
    uint32_t* Bf    = (uint32_t*)(smraw + HALO_H * 2);

    const int x0 = blockIdx.x * 16;
    const int y0 = blockIdx.y * 8;
    const int b  = blockIdx.z / SPLIT;
    const int cb = blockIdx.z % SPLIT;
    const int co0 = cb * 64;
    const int tid = threadIdx.x;
    const int warp = tid >> 5, lane = tid & 31;
    const int lr = lane >> 2, lc = lane & 3;

    float acc[MFS][8][4] = {};

    int pixoff[MFS][2];
    #pragma unroll
    for (int mf = 0; mf < MFS; mf++)
        #pragma unroll
        for (int r8 = 0; r8 < 2; r8++) {
            int m = warp * 32 + mf * 16 + r8 * 8 + lr;
            int py = m >> 4, px = m & 15;
            pixoff[mf][r8] = (py * HW2 + px) * PSTH;
        }

    for (int ch = 0; ch < CHUNKS; ch++) {
        const int cin0 = ch * 64;
        __syncthreads();

        {
            const uint32_t* src = wfrag + (size_t)(0 * CHUNKS * SPLIT + ch * SPLIT + cb) * WTAP;
            #pragma unroll
            for (int i = 0; i < CPT; i++) { int o = (tid + i * 128) * 4; cp16(Bf + o, src + o); }
        }
        // halo via cp.async-zfill (same commit group as tap-0 weights)
        for (int idx = tid * 8; idx < 10 * HW2 * 64; idx += 128 * 8) {
            int c = idx & 63;
            int sp = idx >> 6;
            int hy = sp / HW2, hx = sp - hy * HW2;
            int gy = y0 + hy - 1, gx = x0 + hx - 1;
            bool ok = (unsigned)gy < HH && (unsigned)gx < WW;
            const __half* src = ok ? (in + (((size_t)b * HH + gy) * WW + gx) * CIN + cin0 + c) : in;
            cp16z(haloH + sp * PSTH + c, src, ok ? 16 : 0);
        }
        cp_commit();
        cp_wait0();
        __syncthreads();

        for (int t = 0; t < 9; t++) {
            if (t < 8) {
                uint32_t* nb = Bf + ((t + 1) & 1) * WTAP;
                const uint32_t* src = wfrag + (size_t)((t + 1) * CHUNKS * SPLIT + ch * SPLIT + cb) * WTAP;
                #pragma unroll
                for (int i = 0; i < CPT; i++) { int o = (tid + i * 128) * 4; cp16(nb + o, src + o); }
                cp_commit();
            }

            const uint32_t* Bc = Bf + (t & 1) * WTAP;
            const int toff = ((t / 3) * HW2 + (t % 3)) * PSTH;

            #pragma unroll
            for (int ks16 = 0; ks16 < 4; ks16++) {
                uint32_t a[MFS][4];
                #pragma unroll
                for (int mf = 0; mf < MFS; mf++) {
                    const __half* b0 = haloH + pixoff[mf][0] + toff + ks16 * 16 + 2 * lc;
                    const __half* b1 = haloH + pixoff[mf][1] + toff + ks16 * 16 + 2 * lc;
                    a[mf][0] = *(const uint32_t*)b0;
                    a[mf][1] = *(const uint32_t*)b1;
                    a[mf][2] = *(const uint32_t*)(b0 + 8);
                    a[mf][3] = *(const uint32_t*)(b1 + 8);
                }
                #pragma unroll
                for (int nf = 0; nf < 8; nf++) {
                    uint2 bv = *(const uint2*)&Bc[(ks16 * 8 + nf) * 64 + lane * 2];
                    #pragma unroll
                    for (int mf = 0; mf < MFS; mf++)
                        mma16h(acc[mf][nf], a[mf], bv);
                }
            }

            if (t < 8) { cp_wait0(); __syncthreads(); }
        }
    }

    #pragma unroll
    for (int mf = 0; mf < MFS; mf++) {
        #pragma unroll
        for (int r8 = 0; r8 < 2; r8++) {
            int m = warp * 32 + mf * 16 + r8 * 8 + lr;
            int py = m >> 4, px = m & 15;
            int y = y0 + py, xx = x0 + px;
            size_t base = (((size_t)b * HH + y) * WW + xx) * COUT_TOT + co0;
            #pragma unroll
            for (int nf = 0; nf < 8; nf++) {
                int n = nf * 8 + lc * 2;
                float vx = fmaxf(acc[mf][nf][r8 * 2 + 0] + bias[co0 + n], 0.f);
                float vy = fmaxf(acc[mf][nf][r8 * 2 + 1] + bias[co0 + n + 1], 0.f);
                if (OUT_HALF) {
                    __half2 h = __floats2half2_rn(vx, vy);
                    *(__half2*)((__half*)out_ + base + n) = h;
                } else {
                    *(float2*)((float*)out_ + base + n) = make_float2(vx, vy);
                }
            }
        }
    }
}

// ---------------------------------------------------------------------------
// conv3: fp16 3x3 conv, 16x16 tile, 256 threads (R14 form, zfill halo).
// grid = (W/16, H/16, B)
// ---------------------------------------------------------------------------
template <int CIN, int COUT_TOT, bool OUT_HALF>
__global__ __launch_bounds__(256, 2) void conv_fp16_l(
    const __half* __restrict__ in, const uint32_t* __restrict__ wfrag,
    const float* __restrict__ bias, void* __restrict__ out_)
{
    constexpr int HW2 = 18, PSTH = 72;
    constexpr int HALO_H = 18 * HW2 * PSTH;
    constexpr int CHUNKS = CIN / 64;
    constexpr int WTAP = 2048;
    constexpr int CPT = WTAP / 4 / 256;
    constexpr int MFS = 2;

    extern __shared__ char smraw[];
    __half*   haloH = (__half*)smraw;
    uint32_t* Bf    = (uint32_t*)(smraw + HALO_H * 2);

    const int x0 = blockIdx.x * 16;
    const int y0 = blockIdx.y * 16;
    const int b  = blockIdx.z;
    const int tid = threadIdx.x;
    const int warp = tid >> 5, lane = tid & 31;
    const int lr = lane >> 2, lc = lane & 3;

    float acc[MFS][8][4] = {};

    int pixoff[MFS][2];
    #pragma unroll
    for (int mf = 0; mf < MFS; mf++)
        #pragma unroll
        for (int r8 = 0; r8 < 2; r8++) {
            int m = warp * 32 + mf * 16 + r8 * 8 + lr;   // 0..255
            int py = m >> 4, px = m & 15;
            pixoff[mf][r8] = (py * HW2 + px) * PSTH;
        }

    for (int ch = 0; ch < CHUNKS; ch++) {
        const int cin0 = ch * 64;
        __syncthreads();

        {
            const uint32_t* src = wfrag + (size_t)(0 * CHUNKS + ch) * WTAP;
            #pragma unroll
            for (int i = 0; i < CPT; i++) { int o = (tid + i * 256) * 4; cp16(Bf + o, src + o); }
        }
        // halo via cp.async-zfill (same commit group as tap-0 weights)
        for (int idx = tid * 8; idx < 18 * HW2 * 64; idx += 256 * 8) {
            int c = idx & 63;
            int sp = idx >> 6;
            int hy = sp / HW2, hx = sp - hy * HW2;
            int gy = y0 + hy - 1, gx = x0 + hx - 1;
            bool ok = (unsigned)gy < HH && (unsigned)gx < WW;
            const __half* src = ok ? (in + (((size_t)b * HH + gy) * WW + gx) * CIN + cin0 + c) : in;
            cp16z(haloH + sp * PSTH + c, src, ok ? 16 : 0);
        }
        cp_commit();
        cp_wait0();
        __syncthreads();

        for (int t = 0; t < 9; t++) {
            if (t < 8) {
                uint32_t* nb = Bf + ((t + 1) & 1) * WTAP;
                const uint32_t* src = wfrag + (size_t)((t + 1) * CHUNKS + ch) * WTAP;
                #pragma unroll
                for (int i = 0; i < CPT; i++) { int o = (tid + i * 256) * 4; cp16(nb + o, src + o); }
                cp_commit();
            }

            const uint32_t* Bc = Bf + (t & 1) * WTAP;
            const int toff = ((t / 3) * HW2 + (t % 3)) * PSTH;

            #pragma unroll
            for (int ks16 = 0; ks16 < 4; ks16++) {
                uint32_t a[MFS][4];
                #pragma unroll
                for (int mf = 0; mf < MFS; mf++) {
                    const __half* b0 = haloH + pixoff[mf][0] + toff + ks16 * 16 + 2 * lc;
                    const __half* b1 = haloH + pixoff[mf][1] + toff + ks16 * 16 + 2 * lc;
                    a[mf][0] = *(const uint32_t*)b0;
                    a[mf][1] = *(const uint32_t*)b1;
                    a[mf][2] = *(const uint32_t*)(b0 + 8);
                    a[mf][3] = *(const uint32_t*)(b1 + 8);
                }
                #pragma unroll
                for (int nf = 0; nf < 8; nf++) {
                    uint2 bv = *(const uint2*)&Bc[(ks16 * 8 + nf) * 64 + lane * 2];
                    #pragma unroll
                    for (int mf = 0; mf < MFS; mf++)
                        mma16h(acc[mf][nf], a[mf], bv);
                }
            }

            if (t < 8) { cp_wait0(); __syncthreads(); }
        }
    }

    #pragma unroll
    for (int mf = 0; mf < MFS; mf++) {
        #pragma unroll
        for (int r8 = 0; r8 < 2; r8++) {
            int m = warp * 32 + mf * 16 + r8 * 8 + lr;
            int py = m >> 4, px = m & 15;
            int y = y0 + py, xx = x0 + px;
            size_t base = (((size_t)b * HH + y) * WW + xx) * COUT_TOT;
            #pragma unroll
            for (int nf = 0; nf < 8; nf++) {
                int n = nf * 8 + lc * 2;
                float vx = fmaxf(acc[mf][nf][r8 * 2 + 0] + bias[n], 0.f);
                float vy = fmaxf(acc[mf][nf][r8 * 2 + 1] + bias[n + 1], 0.f);
                if (OUT_HALF) {
                    __half2 h = __floats2half2_rn(vx, vy);
                    *(__half2*)((__half*)out_ + base + n) = h;
                } else {
                    *(float2*)((float*)out_ + base + n) = make_float2(vx, vy);
                }
            }
        }
    }
}

// ---------------------------------------------------------------------------
// Launch
// ---------------------------------------------------------------------------
extern "C" void kernel_launch(void* const* d_in, const int* in_sizes, int n_in,
                              void* d_out, int out_size)
{
    const float* x      = (const float*)d_in[0];
    const float* K_P    = (const float*)d_in[1];
    const float* V_P    = (const float*)d_in[2];
    const float* Q_P    = (const float*)d_in[3];
    const float* ff1_k  = (const float*)d_in[4];
    const float* ff1_b  = (const float*)d_in[5];
    const float* ff2_k  = (const float*)d_in[6];
    const float* ff2_b  = (const float*)d_in[7];
    const float* ff3_k  = (const float*)d_in[8];
    const float* ff3_b  = (const float*)d_in[9];
    float* out = (float*)d_out;

    __half *t1, *t2, *wKh, *wVh, *wQh, *wF1h, *wc2h, *wc3h;
    cudaGetSymbolAddress((void**)&t1,   g_t1);
    cudaGetSymbolAddress((void**)&t2,   g_t2);
    cudaGetSymbolAddress((void**)&wKh,  g_wKh);
    cudaGetSymbolAddress((void**)&wVh,  g_wVh);
    cudaGetSymbolAddress((void**)&wQh,  g_wQh);
    cudaGetSymbolAddress((void**)&wF1h, g_wF1h);
    cudaGetSymbolAddress((void**)&wc2h, g_wc2h);
    cudaGetSymbolAddress((void**)&wc3h, g_wc3h);

    const int FUSED_SMEM = 180 * 72 * 2 + 4 * 2048 * 4;      // 58688
    const int CONV2_SMEM = 10 * 18 * 72 * 2 + 2 * 2048 * 4;  // 42304
    const int CONV3_SMEM = 18 * 18 * 72 * 2 + 2 * 2048 * 4;  // 63040

    cudaFuncSetAttribute(attn_fused, cudaFuncAttributeMaxDynamicSharedMemorySize, FUSED_SMEM);
    cudaFuncSetAttribute((conv_fp16_s<64, 128, 2, true>), cudaFuncAttributeMaxDynamicSharedMemorySize, CONV2_SMEM);
    cudaFuncSetAttribute((conv_fp16_l<128, 64, false>),   cudaFuncAttributeMaxDynamicSharedMemorySize, CONV3_SMEM);

    // Vectorized weight prep (114688 packed words / 448 blocks)
    prep_w<<<448, 256>>>(K_P, V_P, Q_P, ff1_k, ff2_k, ff3_k);

    // Fused fp16 projections + online-softmax attention + ff1
    attn_fused<<<dim3(WW / 16, HH / 8, BB), 256, FUSED_SMEM>>>(
        x, (const uint32_t*)wQh, (const uint32_t*)wKh, (const uint32_t*)wVh,
        (const uint32_t*)wF1h, ff1_b, t1);

    // conv2 (128-thread form) + conv3 (256-thread form), zfill halos
    conv_fp16_s<64, 128, 2, true><<<dim3(WW / 16, HH / 8, BB * 2), 128, CONV2_SMEM>>>(
        t1, (const uint32_t*)wc2h, ff2_b, t2);
    conv_fp16_l<128, 64, false><<<dim3(WW / 16, HH / 16, BB), 256, CONV3_SMEM>>>(
        t2, (const uint32_t*)wc3h, ff3_b, out);
}